// round 17
// baseline (speedup 1.0000x reference)
#include <cuda_runtime.h>
#include <cuda_bf16.h>
#include <math.h>
#include <stdint.h>

#define H_IN 321
#define W_IN 321
#define WS 41
#define NPIX 1681
#define NPIXP 1696              /* 106*16: padded i extent for psum */
#define NCH 21
#define CP 24
#define NBATCH 16
#define NITERS 10

#define INVSC (321.0f/41.0f)
#define AG 8.0f                 /* 1/(2*(3/12)^2) */
#define ABF 0.011250f           /* 1/(2*(80/12)^2) */
#define BBF (1.0f/338.0f)       /* 1/(2*13^2) */
#define CG 3.0f
#define CB 10.0f
#define EPSV 1e-5f

#define KPAD 1728               /* 27*64: padded k extent of K and Qcm */
#define MPAD 1792               /* 28*64: padded row extent of K */
#define NCHUNK 27
#define TI 16                   /* kbraw/knorm i-tile */
#define NLB 64
#define ASTR 72                 /* padded smem row stride (bf16 elems), 72*2=144B */
#define TM 64                   /* k_mma row tile */
#define NSTAGE 6                /* cp.async pipeline depth */
#define KB_GX 4                 /* j-slices for kbraw partial sums: 4*256 >= KPAD/2 */

__device__ __forceinline__ int div41(int j) { return (j*51151) >> 21; }

// ---------------- static device buffers ----------------
static __device__ float  g_colors[NBATCH*NPIX*4];
static __device__ float2 g_pos[NPIX];
static __device__ float  g_rsg[NPIX];
static __device__ float  g_rsb[NBATCH*NPIX];
static __device__ float  g_psum[KB_GX*NBATCH*NPIXP];      // deterministic partial row sums
static __device__ float  g_probs[NBATCH*NPIX*CP];
static __device__ float  g_logu[NBATCH*NPIX*CP];
static __device__ float  g_Qa[NBATCH*NPIX*CP];            // row-major fp32 Q (for loss)
static __device__ float  g_lpart[NLB];
static __device__ unsigned short g_Kh[(size_t)NBATCH*MPAD*KPAD];      // bf16 Kb -> Keff
static __device__ unsigned short g_Qcm[(size_t)2*NBATCH*32*KPAD];     // bf16 Q channel-major x2

__device__ __forceinline__ uint32_t s2u(const void* p) {
    uint32_t a;
    asm("{ .reg .u64 t; cvta.to.shared.u64 t, %1; cvt.u32.u64 %0, t; }" : "=r"(a) : "l"(p));
    return a;
}
__device__ __forceinline__ void cp16(uint32_t dst, const void* src) {
    asm volatile("cp.async.cg.shared.global [%0], [%1], 16;" :: "r"(dst), "l"(src));
}

// ---------------- setup ----------------

__global__ void k_rsg() {
    int i = blockIdx.x*blockDim.x + threadIdx.x;
    if (i >= NPIX) return;
    int y = div41(i), x = i - y*41;
    g_pos[i] = make_float2((float)x, (float)y);
    float Sx = 0.f, Sy = 0.f;
    for (int j = 0; j < WS; j++) {
        int dx = x - j; Sx += expf(-AG * (float)(dx*dx));
        int dy = y - j; Sy += expf(-AG * (float)(dy*dy));
    }
    g_rsg[i] = rsqrtf(Sx*Sy - 1.0f);
}

__global__ void k_resize(const float* __restrict__ img) {
    int t = blockIdx.x*blockDim.x + threadIdx.x;
    if (t >= NBATCH*NPIX) return;
    int n = t / NPIX, p = t - n*NPIX;
    int oy = div41(p), ox = p - oy*41;

    float wy[18], wx[18];
    float sy = (oy + 0.5f)*INVSC - 0.5f;
    int jy0 = max(0, (int)ceilf(sy - INVSC));
    int jy1 = min(H_IN-1, (int)floorf(sy + INVSC));
    float sumy = 0.f;
    for (int j = jy0; j <= jy1; j++) {
        float w = fmaxf(1.0f - fabsf(sy - (float)j)*(1.0f/INVSC), 0.f);
        wy[j-jy0] = w; sumy += w;
    }
    float sx = (ox + 0.5f)*INVSC - 0.5f;
    int jx0 = max(0, (int)ceilf(sx - INVSC));
    int jx1 = min(W_IN-1, (int)floorf(sx + INVSC));
    float sumx = 0.f;
    for (int j = jx0; j <= jx1; j++) {
        float w = fmaxf(1.0f - fabsf(sx - (float)j)*(1.0f/INVSC), 0.f);
        wx[j-jx0] = w; sumx += w;
    }

    float a0 = 0.f, a1 = 0.f, a2 = 0.f;
    const float* b0 = img + (size_t)(n*3 + 0)*H_IN*W_IN;
    const float* b1 = img + (size_t)(n*3 + 1)*H_IN*W_IN;
    const float* b2 = img + (size_t)(n*3 + 2)*H_IN*W_IN;
    for (int jy = jy0; jy <= jy1; jy++) {
        float wyv = wy[jy-jy0];
        const float* r0 = b0 + (size_t)jy*W_IN;
        const float* r1 = b1 + (size_t)jy*W_IN;
        const float* r2 = b2 + (size_t)jy*W_IN;
        for (int jx = jx0; jx <= jx1; jx++) {
            float w = wyv * wx[jx-jx0];
            a0 = fmaf(w, r0[jx], a0);
            a1 = fmaf(w, r1[jx], a1);
            a2 = fmaf(w, r2[jx], a2);
        }
    }
    float inv = 1.0f/(sumy*sumx);
    float4 c; c.x = a0*inv; c.y = a1*inv; c.z = a2*inv; c.w = 0.f;
    ((float4*)g_colors)[t] = c;
}

// zero both Qcm buffers (pads stay zero through the run)
__global__ void k_qzero() {
    size_t t = (size_t)blockIdx.x*256 + threadIdx.x;
    size_t tot = (size_t)2*NBATCH*32*KPAD/8;
    if (t < tot) ((uint4*)g_Qcm)[t] = make_uint4(0,0,0,0);
}

__global__ void k_probs(const float* __restrict__ pred) {
    int t = blockIdx.x*blockDim.x + threadIdx.x;
    if (t >= NBATCH*NPIX) return;
    int n = t / NPIX, p = t - n*NPIX;
    const float* base = pred + (size_t)n*NCH*NPIX + p;
    float x[NCH];
    float m = -1e30f;
    #pragma unroll
    for (int c = 0; c < NCH; c++) { x[c] = base[(size_t)c*NPIX]; m = fmaxf(m, x[c]); }
    float s = 0.f;
    #pragma unroll
    for (int c = 0; c < NCH; c++) { x[c] = __expf(x[c]-m); s += x[c]; }
    float inv = 1.0f/s;
    float s2 = 0.f;
    #pragma unroll
    for (int c = 0; c < NCH; c++) { x[c] = fminf(fmaxf(x[c]*inv, EPSV), 1.0f); s2 += x[c]; }
    float inv2 = 1.0f/s2;
    float* pp = g_probs + (size_t)t*CP;
    float* pl = g_logu  + (size_t)t*CP;
    unsigned short* qc = g_Qcm + (size_t)n*32*KPAD;   // buffer 0
    #pragma unroll
    for (int c = 0; c < NCH; c++) {
        float v = x[c]*inv2;
        pp[c] = v; pl[c] = __logf(v);
        unsigned int b;
        asm("cvt.rn.bf16x2.f32 %0, %1, %2;" : "=r"(b) : "f"(0.f), "f"(v));
        qc[(size_t)c*KPAD + p] = (unsigned short)(b & 0xffffu);
    }
    #pragma unroll
    for (int c = NCH; c < CP; c++) { pp[c] = 0.f; pl[c] = 0.f; }
}

// ---------------- Kb pass 1: bilateral exp once, bf16 store + partial row sums ----------------
__global__ void __launch_bounds__(256) k_kbraw() {
    __shared__ float4 Ci[TI];
    __shared__ float2 Pi[TI];
    __shared__ float  red[TI][8];
    int n = blockIdx.z;
    int i0 = blockIdx.y*TI;
    int tid = threadIdx.x;
    int jp = blockIdx.x*256 + tid;
    const float4* cols = ((const float4*)g_colors) + (size_t)n*NPIX;
    if (tid < TI) {
        int ii = min(i0 + tid, NPIX-1);
        Ci[tid] = cols[ii];
        Pi[tid] = g_pos[ii];
    }
    __syncthreads();
    bool jvalid = (jp < KPAD/2);
    int j0 = 2*jp, j1 = j0 + 1;
    int j0c = min(j0, NPIX-1), j1c = min(j1, NPIX-1);
    float4 cA = cols[j0c], cB = cols[j1c];
    float2 pA = g_pos[j0c], pB = g_pos[j1c];
    unsigned int* out = (unsigned int*)(g_Kh + ((size_t)n*MPAD + i0)*KPAD) + jp;

    float ps[TI];
    #pragma unroll 4
    for (int ii = 0; ii < TI; ii++) {
        int i = i0 + ii;
        float v0 = 0.f, v1 = 0.f;
        if (jvalid && i < NPIX) {
            float4 ci = Ci[ii]; float2 pi = Pi[ii];
            {
                float dy = pi.y - pA.y, dx = pi.x - pA.x;
                float dr = ci.x - cA.x, dg = ci.y - cA.y, db = ci.z - cA.z;
                float d2 = fmaf(dy, dy, dx*dx);
                float cd2 = fmaf(dr, dr, fmaf(dg, dg, db*db));
                v0 = __expf(fmaf(-ABF, d2, -BBF*cd2));
                if (j0 >= NPIX || j0 == i) v0 = 0.f;
            }
            {
                float dy = pi.y - pB.y, dx = pi.x - pB.x;
                float dr = ci.x - cB.x, dg = ci.y - cB.y, db = ci.z - cB.z;
                float d2 = fmaf(dy, dy, dx*dx);
                float cd2 = fmaf(dr, dr, fmaf(dg, dg, db*db));
                v1 = __expf(fmaf(-ABF, d2, -BBF*cd2));
                if (j1 >= NPIX || j1 == i) v1 = 0.f;
            }
        }
        ps[ii] = v0 + v1;
        if (jvalid) {
            unsigned int pk;
            asm("cvt.rn.bf16x2.f32 %0, %1, %2;" : "=r"(pk) : "f"(v1), "f"(v0));
            out[(size_t)ii*(KPAD/2)] = pk;
        }
    }

    // block-reduce per-i partial sums (deterministic, no atomics)
    int wid = tid >> 5, lane = tid & 31;
    #pragma unroll
    for (int ii = 0; ii < TI; ii++) {
        float v = ps[ii];
        for (int o = 16; o; o >>= 1) v += __shfl_down_sync(0xffffffffu, v, o);
        if (lane == 0) red[ii][wid] = v;
    }
    __syncthreads();
    if (tid < TI) {
        float s = 0.f;
        #pragma unroll
        for (int w8 = 0; w8 < 8; w8++) s += red[tid][w8];
        g_psum[((size_t)blockIdx.x*NBATCH + n)*NPIXP + i0 + tid] = s;
    }
}

// combine 4 partial-sum slices -> rsb (fixed order = deterministic)
__global__ void k_rsbf() {
    int t = blockIdx.x*256 + threadIdx.x;
    if (t >= NBATCH*NPIX) return;
    int n = t / NPIX, i = t - n*NPIX;
    float s = 0.f;
    #pragma unroll
    for (int b = 0; b < KB_GX; b++)
        s += g_psum[((size_t)b*NBATCH + n)*NPIXP + i];
    g_rsb[t] = rsqrtf(s);
}

// ---------------- Kb pass 2: normalize + gaussian, in place ----------------
__global__ void __launch_bounds__(256) k_knorm() {
    __shared__ float2 Pi[TI];
    __shared__ float  Rb[TI], Rg[TI];
    int n = blockIdx.z;
    int i0 = blockIdx.y*TI;
    int tid = threadIdx.x;
    int jp = blockIdx.x*256 + tid;
    if (tid < TI) {
        int ii = min(i0 + tid, NPIX-1);
        Pi[tid] = g_pos[ii];
        Rb[tid] = g_rsb[n*NPIX + ii];
        Rg[tid] = g_rsg[ii];
    }
    __syncthreads();
    if (jp >= KPAD/2) return;
    int j0 = 2*jp, j1 = j0 + 1;
    int j0c = min(j0, NPIX-1), j1c = min(j1, NPIX-1);
    float2 pA = g_pos[j0c], pB = g_pos[j1c];
    float rbA = g_rsb[n*NPIX+j0c], rbB = g_rsb[n*NPIX+j1c];
    float rgA = g_rsg[j0c], rgB = g_rsg[j1c];
    unsigned int* buf = (unsigned int*)(g_Kh + ((size_t)n*MPAD + i0)*KPAD) + jp;
    #pragma unroll 4
    for (int ii = 0; ii < TI; ii++) {
        int i = i0 + ii;
        unsigned int pk = buf[(size_t)ii*(KPAD/2)];
        float v0 = 0.f, v1 = 0.f;
        if (i < NPIX) {
            float kb0 = __uint_as_float(pk << 16);
            float kb1 = __uint_as_float(pk & 0xffff0000u);
            float2 pi = Pi[ii];
            float rbi = Rb[ii], rgi = Rg[ii];
            {
                float dy = pi.y - pA.y, dx = pi.x - pA.x;
                float d2 = fmaf(dy, dy, dx*dx);
                v0 = CB * kb0 * rbi * rbA;
                if (d2 < 12.5f) v0 = fmaf(CG, __expf(-AG*d2)*rgi*rgA, v0);
                if (j0 >= NPIX || j0 == i) v0 = 0.f;
            }
            {
                float dy = pi.y - pB.y, dx = pi.x - pB.x;
                float d2 = fmaf(dy, dy, dx*dx);
                v1 = CB * kb1 * rbi * rbB;
                if (d2 < 12.5f) v1 = fmaf(CG, __expf(-AG*d2)*rgi*rgB, v1);
                if (j1 >= NPIX || j1 == i) v1 = 0.f;
            }
        }
        unsigned int pk2;
        asm("cvt.rn.bf16x2.f32 %0, %1, %2;" : "=r"(pk2) : "f"(v1), "f"(v0));
        buf[(size_t)ii*(KPAD/2)] = pk2;
    }
}

// ---------------- fused msg GEMM (mma.sync bf16, cp.async 6-stage) — R16 exact ----------------
__global__ void __launch_bounds__(128) k_mma(int dir) {
    extern __shared__ unsigned short sm[];
    unsigned short* As = sm;                       // NSTAGE x TM x ASTR
    unsigned short* Bs = sm + NSTAGE*TM*ASTR;      // NSTAGE x 24 x ASTR
    int tid = threadIdx.x;
    int lane = tid & 31, w = tid >> 5;
    int n = blockIdx.y, m0 = blockIdx.x*TM;
    const unsigned short* Kn = g_Kh + ((size_t)n*MPAD + m0)*KPAD;
    const unsigned short* Qc = g_Qcm + ((size_t)dir*NBATCH + n)*32*KPAD;
    unsigned short*       Qo = g_Qcm + ((size_t)(dir^1)*NBATCH + n)*32*KPAD;

    uint32_t asBase = s2u(As), bsBase = s2u(Bs);

    auto issue = [&](int ch, int b) {
        uint32_t Ad = asBase + (uint32_t)(b*TM*ASTR*2);
        uint32_t Bd = bsBase + (uint32_t)(b*24*ASTR*2);
        const unsigned short* Ks = Kn + ch*64;
        const unsigned short* Qs = Qc + ch*64;
        #pragma unroll
        for (int r = 0; r < 4; r++) {                 // A: 64 rows x 8 x 16B = 512
            int u = tid + 128*r, row = u >> 3, g = u & 7;
            cp16(Ad + (uint32_t)((row*ASTR + g*8)*2), Ks + (size_t)row*KPAD + g*8);
        }
        {                                             // B: 24 rows x 8 x 16B = 192
            int u = tid, row = u >> 3, g = u & 7;
            cp16(Bd + (uint32_t)((row*ASTR + g*8)*2), Qs + (size_t)row*KPAD + g*8);
            u = tid + 128;
            if (u < 192) {
                row = u >> 3; g = u & 7;
                cp16(Bd + (uint32_t)((row*ASTR + g*8)*2), Qs + (size_t)row*KPAD + g*8);
            }
        }
    };

    float acc[3][4];
    #pragma unroll
    for (int g = 0; g < 3; g++)
        #pragma unroll
        for (int i = 0; i < 4; i++) acc[g][i] = 0.f;

    #pragma unroll
    for (int s = 0; s < NSTAGE-1; s++) {
        issue(s, s);
        asm volatile("cp.async.commit_group;" ::: "memory");
    }

    int b = 0;
    int bn = NSTAGE-1;
    for (int ch = 0; ch < NCHUNK; ch++) {
        asm volatile("cp.async.wait_group %0;" :: "n"(NSTAGE-2) : "memory");
        __syncthreads();
        uint32_t Ab = asBase + (uint32_t)(b*TM*ASTR*2);
        uint32_t Bb = bsBase + (uint32_t)(b*24*ASTR*2);
        #pragma unroll
        for (int kk = 0; kk < 4; kk++) {
            uint32_t a0,a1,a2,a3;
            uint32_t aaddr = Ab + (uint32_t)(((w*16 + (lane & 15))*ASTR + kk*16 + (lane >> 4)*8)*2);
            asm volatile("ldmatrix.sync.aligned.m8n8.x4.shared.b16 {%0,%1,%2,%3}, [%4];"
                         : "=r"(a0),"=r"(a1),"=r"(a2),"=r"(a3) : "r"(aaddr));
            #pragma unroll
            for (int g = 0; g < 3; g++) {
                uint32_t b0,b1;
                uint32_t baddr = Bb + (uint32_t)((((g*8 + (lane>>2)))*ASTR + kk*16 + (lane&3)*2)*2);
                asm volatile("ld.shared.b32 %0, [%1];" : "=r"(b0) : "r"(baddr));
                asm volatile("ld.shared.b32 %0, [%1];" : "=r"(b1) : "r"(baddr + 16));
                asm volatile("mma.sync.aligned.m16n8k16.row.col.f32.bf16.bf16.f32 "
                             "{%0,%1,%2,%3}, {%4,%5,%6,%7}, {%8,%9}, {%0,%1,%2,%3};"
                             : "+f"(acc[g][0]),"+f"(acc[g][1]),"+f"(acc[g][2]),"+f"(acc[g][3])
                             : "r"(a0),"r"(a1),"r"(a2),"r"(a3), "r"(b0),"r"(b1));
            }
        }
        if (ch + NSTAGE-1 < NCHUNK) issue(ch + NSTAGE-1, bn);
        asm volatile("cp.async.commit_group;" ::: "memory");
        if (++b == NSTAGE) b = 0;
        if (++bn == NSTAGE) bn = 0;
    }

    int q = lane & 3;
    int r_lo = m0 + w*16 + (lane >> 2);
    const float* lgB = g_logu + (size_t)n*NPIX*CP;
    float* qaB = g_Qa + (size_t)n*NPIX*CP;

    #pragma unroll
    for (int half = 0; half < 2; half++) {
        int row = r_lo + half*8;
        int rowc = min(row, NPIX-1);
        const float* lg = lgB + (size_t)rowc*CP;
        float lt[6];
        #pragma unroll
        for (int g = 0; g < 3; g++) {
            int c0 = 8*g + 2*q;
            float2 l2 = *(const float2*)(lg + c0);
            lt[2*g]   = (c0   < NCH) ? l2.x + acc[g][half*2]   : -1e30f;
            lt[2*g+1] = (c0+1 < NCH) ? l2.y + acc[g][half*2+1] : -1e30f;
        }
        float mx = lt[0];
        #pragma unroll
        for (int i = 1; i < 6; i++) mx = fmaxf(mx, lt[i]);
        mx = fmaxf(mx, __shfl_xor_sync(0xffffffffu, mx, 1));
        mx = fmaxf(mx, __shfl_xor_sync(0xffffffffu, mx, 2));
        float e[6], s = 0.f;
        #pragma unroll
        for (int i = 0; i < 6; i++) { e[i] = __expf(lt[i]-mx); s += e[i]; }
        s += __shfl_xor_sync(0xffffffffu, s, 1);
        s += __shfl_xor_sync(0xffffffffu, s, 2);
        float inv = 1.0f/s;
        if (row < NPIX) {
            float* o = qaB + (size_t)row*CP;
            #pragma unroll
            for (int g = 0; g < 3; g++) {
                int c0 = 8*g + 2*q;
                float p0 = e[2*g]*inv, p1 = e[2*g+1]*inv;
                *(float2*)(o + c0) = make_float2(p0, p1);
                if (c0 < NCH) {
                    unsigned int b2;
                    asm("cvt.rn.bf16x2.f32 %0, %1, %2;" : "=r"(b2) : "f"(p1), "f"(p0));
                    Qo[(size_t)c0*KPAD + row] = (unsigned short)(b2 & 0xffffu);
                    if (c0 + 1 < NCH)
                        Qo[(size_t)(c0+1)*KPAD + row] = (unsigned short)(b2 >> 16);
                }
            }
        }
    }
}

// ---------------- loss ----------------
__global__ void k_loss1() {
    int tid = threadIdx.x;
    float part = 0.f;
    for (int t = blockIdx.x*256 + tid; t < NBATCH*NPIX; t += NLB*256) {
        const float* q  = g_Qa    + (size_t)t*CP;
        const float* pr = g_probs + (size_t)t*CP;
        float ps[NCH];
        float s = 0.f;
        #pragma unroll
        for (int c = 0; c < NCH; c++) { ps[c] = fmaxf(q[c], EPSV); s += ps[c]; }
        float inv = 1.0f/s;
        #pragma unroll
        for (int c = 0; c < NCH; c++) {
            float p = ps[c]*inv;
            float r = p/pr[c];
            r = fminf(fmaxf(r, 0.05f), 20.0f);
            part += p*__logf(r);
        }
    }
    for (int o = 16; o; o >>= 1) part += __shfl_down_sync(0xffffffffu, part, o);
    __shared__ float red[8];
    int wid = tid >> 5, lane = tid & 31;
    if (lane == 0) red[wid] = part;
    __syncthreads();
    if (wid == 0) {
        float v = (lane < 8) ? red[lane] : 0.f;
        for (int o = 4; o; o >>= 1) v += __shfl_down_sync(0xffffffffu, v, o);
        if (lane == 0) g_lpart[blockIdx.x] = v;
    }
}

__global__ void k_loss2(float* __restrict__ out) {
    int lane = threadIdx.x;   // 64 threads
    float v = g_lpart[lane];
    for (int o = 16; o; o >>= 1) v += __shfl_down_sync(0xffffffffu, v, o);
    __shared__ float red[2];
    if ((lane & 31) == 0) red[lane >> 5] = v;
    __syncthreads();
    if (lane == 0) out[0] = (red[0] + red[1]) / (float)(NBATCH*NPIX);
}

extern "C" void kernel_launch(void* const* d_in, const int* in_sizes, int n_in,
                              void* d_out, int out_size) {
    const float* images  = (const float*)d_in[0];
    const float* predict = (const float*)d_in[1];
    if (n_in >= 2 && in_sizes[0] < in_sizes[1]) {
        const float* tmp = images; images = predict; predict = tmp;
    }

    const int SMEM = NSTAGE*(TM + 24)*ASTR*2;   // 76032 B
    cudaFuncSetAttribute(k_mma, cudaFuncAttributeMaxDynamicSharedMemorySize, SMEM);

    k_rsg<<<(NPIX + 255)/256, 256>>>();
    k_resize<<<(NBATCH*NPIX + 127)/128, 128>>>(images);
    k_qzero<<<(int)(((size_t)2*NBATCH*32*KPAD/8 + 255)/256), 256>>>();
    k_probs<<<(NBATCH*NPIX + 127)/128, 128>>>(predict);
    k_kbraw<<<dim3(KB_GX, NPIXP/TI, NBATCH), 256>>>();
    k_rsbf<<<(NBATCH*NPIX + 255)/256, 256>>>();
    k_knorm<<<dim3(KB_GX, NPIXP/TI, NBATCH), 256>>>();
    for (int it = 0; it < NITERS; it++) {
        k_mma<<<dim3(MPAD/TM, NBATCH), 128, SMEM>>>(it & 1);
    }
    k_loss1<<<NLB, 256>>>();
    k_loss2<<<1, 64>>>((float*)d_out);
}